// round 9
// baseline (speedup 1.0000x reference)
#include <cuda_runtime.h>
#include <math.h>
#include <stdint.h>

#define Bz 64
#define Lz 500
#define Dz 300
#define Fz 100
#define IDz 32

// K3 GEMM geometry
#define NP 112          // padded N (F=100 -> 112 = 2 warps x 7 mma-n-tiles x 8)
#define KSEG 304        // padded per-segment K (D=300 -> 304)
#define KP (3 * KSEG)   // 912 total K
#define AST 308         // a_sm row stride (20r+tg covers all banks)
#define BST 156         // b_sm row stride (28g+tg covers all banks)

// ---------------- scratch (device globals; no allocation) ----------------
__device__ __align__(16) float g_WTB[2 * 2 * NP * KP];    // [side][pass hi/lo][n][K] tf32-rounded
__device__ __align__(16) float g_FEAT[2 * Bz * Lz * Fz];  // conv features [side][b][l][f]
__device__ float g_SQ[2 * Bz * Lz];                       // sum_f feat^2
__device__ float g_ATT[2 * Bz * Lz];                      // [0]=user rowsum, [1]=item colsum
__device__ float g_COLP[8 * Bz * Lz];                     // per-ltile colsum partials (deterministic)
__device__ float g_S[2 * Bz * 3 * Fz];                    // pooled weighted sums

__device__ __forceinline__ void tf32_split(float x, uint32_t& hi, uint32_t& lo) {
    uint32_t h;
    asm("cvt.rna.tf32.f32 %0, %1;" : "=r"(h) : "f"(x));
    float r = x - __uint_as_float(h);
    uint32_t l;
    asm("cvt.rna.tf32.f32 %0, %1;" : "=r"(l) : "f"(r));
    hi = h; lo = l;
}

__device__ __forceinline__ uint32_t to_tf32(float x) {
    uint32_t h;
    asm("cvt.rna.tf32.f32 %0, %1;" : "=r"(h) : "f"(x));
    return h;
}

__device__ __forceinline__ void mma_tf32(float* c, const uint32_t* a, const uint32_t* b) {
    asm("mma.sync.aligned.m16n8k8.row.col.f32.tf32.tf32.f32 "
        "{%0,%1,%2,%3},{%4,%5,%6,%7},{%8,%9},{%0,%1,%2,%3};"
        : "+f"(c[0]), "+f"(c[1]), "+f"(c[2]), "+f"(c[3])
        : "r"(a[0]), "r"(a[1]), "r"(a[2]), "r"(a[3]), "r"(b[0]), "r"(b[1]));
}

// ---------------- KT: build tf32 hi/lo weight planes [side][p][n][K] ----------
__global__ void kt_kernel(const float* __restrict__ wu, const float* __restrict__ wi) {
    int idx = blockIdx.x * 256 + threadIdx.x;
    const int tot = 2 * NP * KP;           // per-side elements (both passes written together)
    if (idx >= tot) return;
    int side = idx / (NP * KP);
    int r = idx % (NP * KP);
    int n = r / KP;
    int K = r % KP;
    int seg = K / KSEG;
    int d = K % KSEG;
    float w = 0.f;
    if (n < Fz && d < Dz) {
        const float* src = side ? wi : wu;
        w = src[(n * 3 + seg) * Dz + d];
    }
    uint32_t hi, lo;
    tf32_split(w, hi, lo);
    long base = (long)side * 2 * NP * KP;
    g_WTB[base + (long)n * KP + K] = __uint_as_float(hi);
    g_WTB[base + (long)(NP + n) * KP + K] = __uint_as_float(lo);
}

// ---------------- K3: fused gather + gate + doc conv (tensor cores) ----------
// block = (ltile of 64, b, side); 256 threads = 8 warps (4 m x 2 n)
__global__ __launch_bounds__(256) void k3_kernel(
    const int* __restrict__ udoc, const int* __restrict__ idoc,
    const float* __restrict__ uemb, const float* __restrict__ iemb,
    const float* __restrict__ wc, const float* __restrict__ wcb,
    const float* __restrict__ udcb, const float* __restrict__ idcb)
{
    extern __shared__ float sm3[];
    float* a_sm = sm3;                       // 68 x AST (rows = l0-2 .. l0+65)
    float* b_sm = a_sm + 68 * AST;           // NP x BST
    float* bias_sm = b_sm + NP * BST;        // NP
    float* t_sm = bias_sm + NP;              // 68 x 3
    float* gate_sm = t_sm + 68 * 3;          // 68
    float* sq_part = gate_sm + 68;           // 2 x 64

    int lt = blockIdx.x, b = blockIdx.y, side = blockIdx.z;
    int l0 = lt * 64;
    const int* doc = (side ? idoc : udoc) + b * Lz;
    const float* emb = side ? iemb : uemb;
    const float* dcb = side ? idcb : udcb;

    int tid = threadIdx.x;
    int w = tid >> 5, lane = tid & 31;
    int wm = w >> 1, wn = w & 1;             // 4 m-warps x 2 n-warps
    int g = lane >> 2, tg = lane & 3;

    // ---- gather 68 embedding rows (cols 0..299), zero cols 300..307 ----
    for (int i = tid; i < 68 * 75; i += 256) {
        int r = i / 75, c = i % 75;
        int l = l0 - 2 + r;
        float4 v = make_float4(0.f, 0.f, 0.f, 0.f);
        if (l >= 0 && l < Lz) {
            const float4* src = (const float4*)(emb + (long)doc[l] * Dz);
            v = src[c];
        }
        ((float4*)(a_sm + r * AST))[c] = v;
    }
    if (tid < 136) {
        int r = tid >> 1, h = tid & 1;
        ((float4*)(a_sm + r * AST + 300))[h] = make_float4(0.f, 0.f, 0.f, 0.f);
    }
    if (tid < NP) bias_sm[tid] = (tid < Fz) ? dcb[tid] : 0.f;
    __syncthreads();

    // ---- t_k[r] = sum_d e[r][d] * wc[k][d] ----
    for (int r = w; r < 68; r += 8) {
        float a0 = 0.f, a1 = 0.f, a2 = 0.f;
        for (int d = lane; d < Dz; d += 32) {
            float ev = a_sm[r * AST + d];
            a0 += ev * wc[d];
            a1 += ev * wc[Dz + d];
            a2 += ev * wc[2 * Dz + d];
        }
        for (int o = 16; o; o >>= 1) {
            a0 += __shfl_xor_sync(0xffffffffu, a0, o);
            a1 += __shfl_xor_sync(0xffffffffu, a1, o);
            a2 += __shfl_xor_sync(0xffffffffu, a2, o);
        }
        if (lane == 0) { t_sm[r * 3 + 0] = a0; t_sm[r * 3 + 1] = a1; t_sm[r * 3 + 2] = a2; }
    }
    __syncthreads();

    // ---- gate rows rr = 1..66 ----
    if (tid < 66) {
        int rr = tid + 1;
        float gg = t_sm[(rr - 1) * 3 + 0] + t_sm[rr * 3 + 1] + t_sm[(rr + 1) * 3 + 2] + wcb[0];
        gate_sm[rr] = 1.f / (1.f + expf(-gg));
    }
    __syncthreads();

    // ---- scale rows 1..66 in place (cols 0..299) ----
    for (int i = tid; i < 66 * 75; i += 256) {
        int r = 1 + i / 75, c = i % 75;
        float gg = gate_sm[r];
        float4* p = (float4*)(a_sm + r * AST) + c;
        float4 v = *p;
        v.x *= gg; v.y *= gg; v.z *= gg; v.w *= gg;
        *p = v;
    }

    // ---- GEMM: acc[M=64][N=112] over K=912, 2 passes (W hi then lo) ----
    float acc[7][4];
#pragma unroll
    for (int j = 0; j < 7; j++)
#pragma unroll
        for (int ci = 0; ci < 4; ci++) acc[j][ci] = 0.f;

    int arow0 = wm * 16 + g;
    const uint32_t* bsm_u = (const uint32_t*)b_sm;

    for (int p = 0; p < 2; p++) {
        const float2* wsrc = (const float2*)(g_WTB + ((long)side * 2 + p) * NP * KP);
        for (int kc = 0; kc < 6; kc++) {
            __syncthreads();
            for (int i = tid; i < NP * 76; i += 256) {
                int n = i / 76, kk = i % 76;
                ((float2*)b_sm)[n * (BST / 2) + kk] = wsrc[(long)n * (KP / 2) + kc * 76 + kk];
            }
            __syncthreads();
#pragma unroll 1
            for (int kt2 = 0; kt2 < 19; kt2++) {
                int ktg = kc * 19 + kt2;
                int seg = ktg / 38;
                int dt = ktg - seg * 38;
                int ar = (arow0 + seg + 1) * AST + dt * 8 + tg;
                uint32_t ua[4];
                ua[0] = to_tf32(a_sm[ar]);
                ua[1] = to_tf32(a_sm[ar + 8 * AST]);
                ua[2] = to_tf32(a_sm[ar + 4]);
                ua[3] = to_tf32(a_sm[ar + 8 * AST + 4]);
                int bk = kt2 * 8 + tg;
#pragma unroll
                for (int j = 0; j < 7; j++) {
                    int n = wn * 56 + j * 8 + g;
                    uint32_t ub[2];
                    ub[0] = bsm_u[n * BST + bk];
                    ub[1] = bsm_u[n * BST + bk + 4];
                    mma_tf32(acc[j], ua, ub);
                }
            }
        }
    }

    // ---- epilogue: bias, store FEAT, per-row sq ----
    long base = (long)(side * Bz + b) * Lz;
    float s0 = 0.f, s1 = 0.f;
    int r0 = arow0, r1 = arow0 + 8;          // block-local l rows
#pragma unroll
    for (int j = 0; j < 7; j++) {
        int f = wn * 56 + j * 8 + 2 * tg;
        float bb0 = bias_sm[f], bb1 = bias_sm[f + 1];
        float x0 = acc[j][0] + bb0, x1 = acc[j][1] + bb1;
        float x2 = acc[j][2] + bb0, x3 = acc[j][3] + bb1;
        if (f < Fz) {                        // f even, so f<100 => f+1<=99
            s0 += x0 * x0 + x1 * x1;
            s1 += x2 * x2 + x3 * x3;
            if (l0 + r0 < Lz)
                *(float2*)(g_FEAT + (base + l0 + r0) * Fz + f) = make_float2(x0, x1);
            if (l0 + r1 < Lz)
                *(float2*)(g_FEAT + (base + l0 + r1) * Fz + f) = make_float2(x2, x3);
        }
    }
    s0 += __shfl_xor_sync(0xffffffffu, s0, 1);
    s0 += __shfl_xor_sync(0xffffffffu, s0, 2);
    s1 += __shfl_xor_sync(0xffffffffu, s1, 1);
    s1 += __shfl_xor_sync(0xffffffffu, s1, 2);
    __syncthreads();
    if (tg == 0) {
        sq_part[wn * 64 + r0] = s0;
        sq_part[wn * 64 + r1] = s1;
    }
    __syncthreads();
    if (tid < 64) {
        int l = l0 + tid;
        if (l < Lz) g_SQ[base + l] = sq_part[tid] + sq_part[64 + tid];
    }
}

// ---------------- K4: pairwise attention row/col sums (tensor cores, 3xTF32) --
#define UST 108

__global__ __launch_bounds__(256) void k4_kernel() {
    extern __shared__ float sm[];
    float* u_sm = sm;                    // 64*UST
    float* v_sm = u_sm + 64 * UST;       // 64*UST
    float* usq = v_sm + 64 * UST;        // 64
    float* vsq = usq + 64;               // 64
    float* red = vsq + 64;               // 8*32
    float* colsm = red + 8 * 32;         // 64

    int lt = blockIdx.x, b = blockIdx.y;
    int l0 = lt * 64;
    int tid = threadIdx.x;
    int w = tid >> 5, lane = tid & 31;
    int wm = w >> 2, wn = w & 3;
    int g = lane >> 2, tg = lane & 3;

    const float* U = g_FEAT + (long)b * Lz * Fz;
    const float* V = g_FEAT + (long)(Bz + b) * Lz * Fz;

    for (int i = tid; i < 64 * Fz; i += 256) {
        int r = i / Fz, c = i % Fz;
        int l = l0 + r;
        u_sm[r * UST + c] = (l < Lz) ? U[l * Fz + c] : 0.f;
    }
    for (int i = tid; i < 64 * (UST - Fz); i += 256) {
        int r = i / (UST - Fz), c = Fz + i % (UST - Fz);
        u_sm[r * UST + c] = 0.f;
        v_sm[r * UST + c] = 0.f;
    }
    if (tid < 64) { int l = l0 + tid; usq[tid] = (l < Lz) ? g_SQ[b * Lz + l] : 0.f; }
    __syncthreads();

    float usq_r[2][2];
#pragma unroll
    for (int mt = 0; mt < 2; mt++)
#pragma unroll
        for (int h = 0; h < 2; h++)
            usq_r[mt][h] = usq[wm * 32 + mt * 16 + g + 8 * h];

    float rowAcc[2][2] = {{0.f, 0.f}, {0.f, 0.f}};
    float colAcc[8][2][2];
#pragma unroll
    for (int vt = 0; vt < 8; vt++)
#pragma unroll
        for (int nt = 0; nt < 2; nt++) { colAcc[vt][nt][0] = 0.f; colAcc[vt][nt][1] = 0.f; }

    for (int vt = 0; vt < 8; vt++) {
        int m0 = vt * 64;
        for (int i = tid; i < 64 * Fz; i += 256) {
            int r = i / Fz, c = i % Fz;
            int m = m0 + r;
            v_sm[r * UST + c] = (m < Lz) ? V[m * Fz + c] : 0.f;
        }
        if (tid < 64) { int m = m0 + tid; vsq[tid] = (m < Lz) ? g_SQ[(Bz + b) * Lz + m] : 0.f; }
        __syncthreads();

        float acc[2][2][4];
#pragma unroll
        for (int mt = 0; mt < 2; mt++)
#pragma unroll
            for (int nt = 0; nt < 2; nt++)
#pragma unroll
                for (int ci = 0; ci < 4; ci++) acc[mt][nt][ci] = 0.f;

#pragma unroll
        for (int kt = 0; kt < 13; kt++) {
            int k0 = kt * 8;
            uint32_t ahi[2][4], alo[2][4];
#pragma unroll
            for (int mt = 0; mt < 2; mt++) {
                int r0 = wm * 32 + mt * 16;
                float a0 = u_sm[(r0 + g) * UST + k0 + tg];
                float a1 = u_sm[(r0 + g + 8) * UST + k0 + tg];
                float a2 = u_sm[(r0 + g) * UST + k0 + tg + 4];
                float a3 = u_sm[(r0 + g + 8) * UST + k0 + tg + 4];
                tf32_split(a0, ahi[mt][0], alo[mt][0]);
                tf32_split(a1, ahi[mt][1], alo[mt][1]);
                tf32_split(a2, ahi[mt][2], alo[mt][2]);
                tf32_split(a3, ahi[mt][3], alo[mt][3]);
            }
            uint32_t bhi[2][2], blo[2][2];
#pragma unroll
            for (int nt = 0; nt < 2; nt++) {
                int nc = wn * 16 + nt * 8 + g;
                float b0 = v_sm[nc * UST + k0 + tg];
                float b1 = v_sm[nc * UST + k0 + tg + 4];
                tf32_split(b0, bhi[nt][0], blo[nt][0]);
                tf32_split(b1, bhi[nt][1], blo[nt][1]);
            }
#pragma unroll
            for (int mt = 0; mt < 2; mt++)
#pragma unroll
                for (int nt = 0; nt < 2; nt++) {
                    mma_tf32(acc[mt][nt], ahi[mt], bhi[nt]);
                    mma_tf32(acc[mt][nt], alo[mt], bhi[nt]);
                    mma_tf32(acc[mt][nt], ahi[mt], blo[nt]);
                }
        }

#pragma unroll
        for (int mt = 0; mt < 2; mt++)
#pragma unroll
            for (int nt = 0; nt < 2; nt++)
#pragma unroll
                for (int ci = 0; ci < 4; ci++) {
                    int h = ci >> 1, e = ci & 1;
                    int lrow = wm * 32 + mt * 16 + g + 8 * h;
                    int lcol = wn * 16 + nt * 8 + 2 * tg + e;
                    int l = l0 + lrow, m = m0 + lcol;
                    float sq = usq_r[mt][h] + vsq[lcol] - 2.f * acc[mt][nt][ci];
                    float a = 1.f / (1.f + sqrtf(fmaxf(sq, 1e-12f)));
                    if (l >= Lz || m >= Lz) a = 0.f;
                    rowAcc[mt][h] += a;
                    colAcc[vt][nt][e] += a;
                }
        __syncthreads();
    }

#pragma unroll
    for (int mt = 0; mt < 2; mt++)
#pragma unroll
        for (int h = 0; h < 2; h++) {
            float s = rowAcc[mt][h];
            s += __shfl_xor_sync(0xffffffffu, s, 1);
            s += __shfl_xor_sync(0xffffffffu, s, 2);
            rowAcc[mt][h] = s;
        }
    if (tg == 0) {
#pragma unroll
        for (int mt = 0; mt < 2; mt++)
#pragma unroll
            for (int h = 0; h < 2; h++)
                red[w * 32 + mt * 16 + 8 * h + g] = rowAcc[mt][h];
    }
    __syncthreads();
    if (tid < 64) {
        int half = tid >> 5, r = tid & 31;
        float s = 0.f;
#pragma unroll
        for (int q = 0; q < 4; q++) s += red[(half * 4 + q) * 32 + r];
        int l = l0 + half * 32 + r;
        if (l < Lz) g_ATT[b * Lz + l] = s;
    }

    for (int vt = 0; vt < 8; vt++) {
        float cs[2][2];
#pragma unroll
        for (int nt = 0; nt < 2; nt++)
#pragma unroll
            for (int e = 0; e < 2; e++) {
                float s = colAcc[vt][nt][e];
                s += __shfl_xor_sync(0xffffffffu, s, 4);
                s += __shfl_xor_sync(0xffffffffu, s, 8);
                s += __shfl_xor_sync(0xffffffffu, s, 16);
                cs[nt][e] = s;
            }
        __syncthreads();
        if (wm == 0 && g == 0) {
#pragma unroll
            for (int nt = 0; nt < 2; nt++)
#pragma unroll
                for (int e = 0; e < 2; e++)
                    colsm[wn * 16 + nt * 8 + 2 * tg + e] = cs[nt][e];
        }
        __syncthreads();
        if (wm == 1 && g == 0) {
#pragma unroll
            for (int nt = 0; nt < 2; nt++)
#pragma unroll
                for (int e = 0; e < 2; e++)
                    colsm[wn * 16 + nt * 8 + 2 * tg + e] += cs[nt][e];
        }
        __syncthreads();
        if (tid < 64) {
            int m = vt * 64 + tid;
            if (m < Lz) g_COLP[((long)lt * Bz + b) * Lz + m] = colsm[tid];
        }
    }
}

// ---------------- K4b: deterministic reduce of colsum partials ----------------
__global__ void k4b_kernel() {
    int i = blockIdx.x * 256 + threadIdx.x;
    if (i >= Bz * Lz) return;
    float s = 0.f;
#pragma unroll
    for (int t = 0; t < 8; t++) s += g_COLP[t * Bz * Lz + i];
    g_ATT[Bz * Lz + i] = s;
}

// ---------------- K5a: pooled weighted sums S_k[b][f] ----------------
__global__ __launch_bounds__(128) void k5a_kernel() {
    int b = blockIdx.x, side = blockIdx.y;
    int f = threadIdx.x;
    if (f >= Fz) return;
    const float* fp = g_FEAT + (long)(side * Bz + b) * Lz * Fz + f;
    const float* ap = g_ATT + (side * Bz + b) * Lz;
    float s0 = 0.f, s1 = 0.f, s2 = 0.f;
    for (int l = 0; l < Lz; l++) {
        float p = fp[l * Fz] * ap[l];
        int lo0 = max(0, l - 1), hi0 = min(497, l + 1);
        int lo1 = max(1, l - 1), hi1 = min(498, l + 1);
        int lo2 = max(2, l - 1), hi2 = min(499, l + 1);
        s0 += (float)max(0, hi0 - lo0 + 1) * p;
        s1 += (float)max(0, hi1 - lo1 + 1) * p;
        s2 += (float)max(0, hi2 - lo2 + 1) * p;
    }
    float* Sb = g_S + (side * Bz + b) * 3 * Fz;
    Sb[f] = s0; Sb[Fz + f] = s1; Sb[2 * Fz + f] = s2;
}

// ---------------- K5b: abs-conv micro-GEMM + FC + id-emb gather + output ------
__global__ __launch_bounds__(128) void k5b_kernel(
    const float* __restrict__ uacw, const float* __restrict__ uacb,
    const float* __restrict__ iacw, const float* __restrict__ iacb,
    const float* __restrict__ ufcw, const float* __restrict__ ufcb,
    const float* __restrict__ ifcw, const float* __restrict__ ifcb,
    const float* __restrict__ uide, const float* __restrict__ iide,
    const int* __restrict__ uids, const int* __restrict__ iids,
    float* __restrict__ out)
{
    int b = blockIdx.x, side = blockIdx.y;
    __shared__ float abar[Fz];
    int tid = threadIdx.x;
    const float* Sb = g_S + (side * Bz + b) * 3 * Fz;
    const float* acw = side ? iacw : uacw;
    const float* acb = side ? iacb : uacb;
    if (tid < Fz) {
        float acc = 0.f;
        for (int t = 0; t < 3 * Fz; t++) acc += Sb[t] * acw[tid * 3 * Fz + t];
        abar[tid] = acb[tid] + acc * (1.f / 498.f);
    }
    __syncthreads();
    int off = side ? (Bz * 2 * IDz) : 0;
    if (tid < IDz) {
        const float* fcw = side ? ifcw : ufcw;
        const float* fcb = side ? ifcb : ufcb;
        float acc = fcb[tid];
        for (int f2 = 0; f2 < Fz; f2++) acc += abar[f2] * fcw[tid * Fz + f2];
        out[off + b * 2 * IDz + tid] = fmaxf(acc, 0.f);
    } else if (tid < 2 * IDz) {
        int id = tid - IDz;
        const float* et = side ? uide : iide;
        const int* ids = side ? uids : iids;
        out[off + b * 2 * IDz + IDz + id] = et[ids[b] * IDz + id];
    }
}

// ---------------- launch ----------------
extern "C" void kernel_launch(void* const* d_in, const int* in_sizes, int n_in,
                              void* d_out, int out_size) {
    const int* uids = (const int*)d_in[0];
    const int* iids = (const int*)d_in[1];
    const int* udoc = (const int*)d_in[2];
    const int* idoc = (const int*)d_in[3];
    const float* uemb = (const float*)d_in[4];
    const float* iemb = (const float*)d_in[5];
    const float* wc   = (const float*)d_in[6];
    const float* wcb  = (const float*)d_in[7];
    const float* udcw = (const float*)d_in[8];
    const float* udcb = (const float*)d_in[9];
    const float* idcw = (const float*)d_in[10];
    const float* idcb = (const float*)d_in[11];
    const float* uacw = (const float*)d_in[12];
    const float* uacb = (const float*)d_in[13];
    const float* iacw = (const float*)d_in[14];
    const float* iacb = (const float*)d_in[15];
    const float* ufcw = (const float*)d_in[16];
    const float* ufcb = (const float*)d_in[17];
    const float* ifcw = (const float*)d_in[18];
    const float* ifcb = (const float*)d_in[19];
    const float* uide = (const float*)d_in[20];
    const float* iide = (const float*)d_in[21];
    float* out = (float*)d_out;

    kt_kernel<<<(2 * NP * KP + 255) / 256, 256>>>(udcw, idcw);

    const int k3_smem = (68 * AST + NP * BST + NP + 68 * 3 + 68 + 128) * (int)sizeof(float);
    cudaFuncSetAttribute(k3_kernel, cudaFuncAttributeMaxDynamicSharedMemorySize, k3_smem);
    dim3 g3(8, Bz, 2);
    k3_kernel<<<g3, 256, k3_smem>>>(udoc, idoc, uemb, iemb, wc, wcb, udcb, idcb);

    const int k4_smem = (2 * 64 * UST + 64 + 64 + 8 * 32 + 64) * (int)sizeof(float);
    cudaFuncSetAttribute(k4_kernel, cudaFuncAttributeMaxDynamicSharedMemorySize, k4_smem);
    dim3 g4(8, Bz);
    k4_kernel<<<g4, 256, k4_smem>>>();

    k4b_kernel<<<(Bz * Lz + 255) / 256, 256>>>();

    dim3 g5(Bz, 2);
    k5a_kernel<<<g5, 128>>>();
    k5b_kernel<<<g5, 128>>>(uacw, uacb, iacw, iacb, ufcw, ufcb, ifcw, ifcb,
                            uide, iide, uids, iids, out);
}